// round 2
// baseline (speedup 1.0000x reference)
#include <cuda_runtime.h>
#include <cuda_bf16.h>
#include <cstdint>

// ============================================================================
// EinetMixture: route each row to nearest centroid (E=8), then compute only
// that expert's Gaussian-leaf log-likelihood (K=64 leaves) + logsumexp.
//
// leaf_ll[b,k] = sum_d ( a[e,k,d]*x^2 + b[e,k,d]*x ) + c[e,k]
//   a = -0.5*exp(-2*ls), b = m*exp(-2*ls), c folded with log_softmax(logits).
// The d-reduction is a bf16 tensor-core GEMM with K-dim interleaved as
// (x[d], x^2[d]) pairs so each u32 MMA operand half-pair is one d.
// ============================================================================

#define B_N 32768
#define D_N 784
#define E_N 8
#define K_N 64
#define F4_PER_ROW 196        // 784/4

#define TILE_M 128
#define CHUNK_D 56            // d's per K4 mainloop chunk (784 = 14*56)
#define NCHUNK 14
#define KSTEPS 7              // k16 steps per chunk (8 d's each)
#define A_PITCH 60            // u32 pitch, %4==0 (16B stores)
#define B_PITCH 72            // u32 pitch, %4==0
#define C_PITCH 66            // float pitch for epilogue

#define LOG_2PI 1.8378770664093453f

// ---------------- device scratch (no allocation allowed) ----------------
__device__ uint32_t d_Wpack[E_N * D_N * K_N];   // [e][d][k] bf16x2 (bcoef, acoef)
__device__ float    d_ccomb[E_N * K_N];         // c + log_softmax(logits)
__device__ float    d_cnorm[E_N];
__device__ int      d_cluster[B_N];
__device__ int      d_counts[E_N];
__device__ int      d_offsets[E_N];
__device__ int      d_cursor[E_N];
__device__ int      d_tileStart[E_N + 1];
__device__ int      d_sortedIdx[B_N];

// ---------------- helpers ----------------
__device__ __forceinline__ uint32_t pack_x_x2(float v) {
    __nv_bfloat162 p = __floats2bfloat162_rn(v, v * v);   // lo = x, hi = x^2
    return *reinterpret_cast<uint32_t*>(&p);
}

__device__ __forceinline__ void mma_bf16(float* c, const uint32_t* a,
                                         uint32_t b0, uint32_t b1) {
    asm volatile(
        "mma.sync.aligned.m16n8k16.row.col.f32.bf16.bf16.f32 "
        "{%0,%1,%2,%3}, {%4,%5,%6,%7}, {%8,%9}, {%0,%1,%2,%3};\n"
        : "+f"(c[0]), "+f"(c[1]), "+f"(c[2]), "+f"(c[3])
        : "r"(a[0]), "r"(a[1]), "r"(a[2]), "r"(a[3]), "r"(b0), "r"(b1));
}

// ============================================================================
// K0: prep weights. grid = E*K CTAs of 128 threads; CTA handles one (e,k).
// ============================================================================
__global__ void __launch_bounds__(128) k0_prep(const float* __restrict__ centroids,
                                               const float* __restrict__ means,
                                               const float* __restrict__ log_stds,
                                               const float* __restrict__ logits) {
    int e = blockIdx.x >> 6;
    int k = blockIdx.x & 63;
    int tid = threadIdx.x;
    __shared__ float red[128];

    const float* mrow = means    + (size_t)(e * K_N + k) * D_N;
    const float* lrow = log_stds + (size_t)(e * K_N + k) * D_N;

    float csum = 0.f;
    for (int d = tid; d < D_N; d += 128) {
        float ls = lrow[d];
        float m  = mrow[d];
        float iv = expf(-2.f * ls);
        float ac = -0.5f * iv;        // coeff of x^2
        float bc = m * iv;            // coeff of x
        csum += -0.5f * m * m * iv - ls;
        __nv_bfloat162 p = __floats2bfloat162_rn(bc, ac);  // lo=b, hi=a
        d_Wpack[((e * D_N + d) << 6) + k] = *reinterpret_cast<uint32_t*>(&p);
    }
    // block reduce csum
    red[tid] = csum;
    __syncthreads();
    for (int s = 64; s; s >>= 1) { if (tid < s) red[tid] += red[tid + s]; __syncthreads(); }
    if (tid == 0) {
        float ctot = red[0];
        const float* lg = logits + e * K_N;
        float mx = lg[0];
        for (int j = 1; j < K_N; j++) mx = fmaxf(mx, lg[j]);
        float s = 0.f;
        for (int j = 0; j < K_N; j++) s += expf(lg[j] - mx);
        float lse = mx + logf(s);
        d_ccomb[e * K_N + k] = ctot - 0.5f * (float)D_N * LOG_2PI + lg[k] - lse;
    }
    __syncthreads();

    // centroid norms (CTAs with k==0 only)
    if (k == 0) {
        const float* crow = centroids + (size_t)e * D_N;
        float cn = 0.f;
        for (int d = tid; d < D_N; d += 128) { float c = crow[d]; cn += c * c; }
        red[tid] = cn;
        __syncthreads();
        for (int s = 64; s; s >>= 1) { if (tid < s) red[tid] += red[tid + s]; __syncthreads(); }
        if (tid == 0) d_cnorm[e] = red[0];
    }
    // zero per-replay counters (K0 runs before K1/K3 every launch)
    if (blockIdx.x == 0 && tid < E_N) { d_counts[tid] = 0; d_cursor[tid] = 0; }
}

// ============================================================================
// K1: routing. One warp per row; centroids staged in smem.
// argmin_e (||c_e||^2 - 2 x.c_e)  ==  argmin_e d2 (||x||^2 is row-constant).
// ============================================================================
__global__ void __launch_bounds__(256) k1_route(const float* __restrict__ x,
                                                const float* __restrict__ centroids) {
    __shared__ float4 cent[E_N * F4_PER_ROW];   // 25088 B
    int tid = threadIdx.x;
    const float4* c4 = reinterpret_cast<const float4*>(centroids);
    for (int j = tid; j < E_N * F4_PER_ROW; j += 256) cent[j] = c4[j];
    __syncthreads();

    int warp = tid >> 5, lane = tid & 31;
    int b = blockIdx.x * 8 + warp;
    const float4* x4 = reinterpret_cast<const float4*>(x) + (size_t)b * F4_PER_ROW;

    float dot[E_N];
#pragma unroll
    for (int e = 0; e < E_N; e++) dot[e] = 0.f;

    for (int j = lane; j < F4_PER_ROW; j += 32) {
        float4 xv = x4[j];
#pragma unroll
        for (int e = 0; e < E_N; e++) {
            float4 cv = cent[e * F4_PER_ROW + j];
            dot[e] += xv.x * cv.x + xv.y * cv.y + xv.z * cv.z + xv.w * cv.w;
        }
    }
#pragma unroll
    for (int e = 0; e < E_N; e++)
#pragma unroll
        for (int o = 16; o; o >>= 1) dot[e] += __shfl_xor_sync(0xffffffffu, dot[e], o);

    if (lane == 0) {
        float best = 3.4e38f;
        int bi = 0;
#pragma unroll
        for (int e = 0; e < E_N; e++) {
            float s = d_cnorm[e] - 2.f * dot[e];
            if (s < best) { best = s; bi = e; }   // strict < => first-min, matches argmin
        }
        d_cluster[b] = bi;
        atomicAdd(&d_counts[bi], 1);
    }
}

// ============================================================================
// K2: exclusive scans (E=8, one thread).
// ============================================================================
__global__ void k2_scan() {
    if (threadIdx.x == 0 && blockIdx.x == 0) {
        int off = 0, ts = 0;
        for (int e = 0; e < E_N; e++) {
            d_offsets[e] = off;
            d_tileStart[e] = ts;
            int c = d_counts[e];
            off += c;
            ts += (c + TILE_M - 1) / TILE_M;
        }
        d_tileStart[E_N] = ts;
    }
}

// ============================================================================
// K3: counting-sort scatter of row indices by expert.
// ============================================================================
__global__ void __launch_bounds__(256) k3_scatter() {
    int b = blockIdx.x * 256 + threadIdx.x;
    int e = d_cluster[b];
    int p = atomicAdd(&d_cursor[e], 1);
    d_sortedIdx[d_offsets[e] + p] = b;
}

// ============================================================================
// K4: grouped GEMM. CTA = 128 gathered rows of one expert, N=64 leaves,
// K-dim = 1568 (pairs (x, x^2) per d), bf16 MMA, fp32 accum.
// 8 warps, warp w owns rows [w*16, w*16+16) x all 64 cols -> acc[8][4].
// Epilogue: + ccomb, logsumexp over 64, scatter to out[original row].
// ============================================================================
__global__ void __launch_bounds__(256) k4_gemm(const float* __restrict__ x,
                                               float* __restrict__ out) {
    __shared__ __align__(16) unsigned char raw[47616];
    uint32_t* As      = reinterpret_cast<uint32_t*>(raw);            // [128][A_PITCH]
    uint32_t* Bs      = reinterpret_cast<uint32_t*>(raw + 30720);    // [56][B_PITCH]
    int*      rowIdxS = reinterpret_cast<int*>(raw + 46848);         // [128]
    float*    ccombS  = reinterpret_cast<float*>(raw + 47360);       // [64]
    float*    Cs      = reinterpret_cast<float*>(raw);               // [128][C_PITCH] epilogue

    int t = blockIdx.x;
    if (t >= d_tileStart[E_N]) return;

    int e = 0;
#pragma unroll
    for (int i = 1; i < E_N; i++) if (t >= d_tileStart[i]) e = i;
    int rowbase = d_offsets[e] + (t - d_tileStart[e]) * TILE_M;
    int nrows = min(TILE_M, d_offsets[e] + d_counts[e] - rowbase);

    int tid = threadIdx.x;
    if (tid < TILE_M)
        rowIdxS[tid] = d_sortedIdx[rowbase + ((tid < nrows) ? tid : 0)];
    if (tid < K_N)
        ccombS[tid] = d_ccomb[e * K_N + tid];
    __syncthreads();

    const uint32_t* Wbase = d_Wpack + (size_t)e * (D_N * K_N);

    int warp = tid >> 5, lane = tid & 31;
    int g = lane >> 2, tig = lane & 3;

    float acc[8][4];
#pragma unroll
    for (int n = 0; n < 8; n++)
#pragma unroll
        for (int q = 0; q < 4; q++) acc[n][q] = 0.f;

    int r = tid >> 1, half = tid & 1;
    const float* xrow = x + (size_t)rowIdxS[r] * D_N;
    int mrow0 = warp * 16;   // warp owns one m16 tile of the 128-row A

    for (int cb = 0; cb < NCHUNK; cb++) {
        int db = cb * CHUNK_D;
        // ---- load A tile: 2 threads per row, 7 float4 each (56 floats/row) ----
#pragma unroll
        for (int q = 0; q < 7; q++) {
            int f4i = half * 7 + q;                       // 0..13
            float4 xv = *reinterpret_cast<const float4*>(xrow + db + f4i * 4);
            uint4 pk;
            pk.x = pack_x_x2(xv.x);
            pk.y = pack_x_x2(xv.y);
            pk.z = pack_x_x2(xv.z);
            pk.w = pack_x_x2(xv.w);
            *reinterpret_cast<uint4*>(&As[r * A_PITCH + f4i * 4]) = pk;
        }
        // ---- load B tile: 56 kk x 64 n (L2-resident weights) ----
        for (int j = tid; j < (CHUNK_D * K_N / 4); j += 256) {  // 896 uint4
            int kk = j >> 4;
            int nq = j & 15;
            uint4 w = *reinterpret_cast<const uint4*>(Wbase + (size_t)(db + kk) * K_N + nq * 4);
            *reinterpret_cast<uint4*>(&Bs[kk * B_PITCH + nq * 4]) = w;
        }
        __syncthreads();

        // ---- MMA: warp handles 16 rows x 64 cols (8 n8), 7 k16 steps ----
#pragma unroll
        for (int ks = 0; ks < KSTEPS; ks++) {
            int kkb = ks * 8;
            uint32_t a[4];
            a[0] = As[(mrow0 + g)     * A_PITCH + kkb + tig];
            a[1] = As[(mrow0 + 8 + g) * A_PITCH + kkb + tig];
            a[2] = As[(mrow0 + g)     * A_PITCH + kkb + tig + 4];
            a[3] = As[(mrow0 + 8 + g) * A_PITCH + kkb + tig + 4];
#pragma unroll
            for (int nt = 0; nt < 8; nt++) {
                uint32_t b0 = Bs[(kkb + tig)     * B_PITCH + nt * 8 + g];
                uint32_t b1 = Bs[(kkb + tig + 4) * B_PITCH + nt * 8 + g];
                mma_bf16(acc[nt], a, b0, b1);
            }
        }
        __syncthreads();
    }

    // ---- epilogue: accums -> smem (Cs aliases As/Bs; all MMA reads done) ----
    {
        int row0 = warp * 16 + g;
#pragma unroll
        for (int nt = 0; nt < 8; nt++) {
            int col = nt * 8 + tig * 2;
            Cs[row0 * C_PITCH + col]           = acc[nt][0];
            Cs[row0 * C_PITCH + col + 1]       = acc[nt][1];
            Cs[(row0 + 8) * C_PITCH + col]     = acc[nt][2];
            Cs[(row0 + 8) * C_PITCH + col + 1] = acc[nt][3];
        }
    }
    __syncthreads();

    // ---- logsumexp per row, scatter to original index ----
    if (tid < TILE_M) {
        const float* crow = &Cs[tid * C_PITCH];
        float mx = -3.4e38f;
#pragma unroll 8
        for (int j = 0; j < K_N; j++) mx = fmaxf(mx, crow[j] + ccombS[j]);
        float s = 0.f;
#pragma unroll 8
        for (int j = 0; j < K_N; j++) s += expf(crow[j] + ccombS[j] - mx);
        float ll = mx + logf(s);
        if (tid < nrows) out[rowIdxS[tid]] = ll;
    }
}

// ============================================================================
extern "C" void kernel_launch(void* const* d_in, const int* in_sizes, int n_in,
                              void* d_out, int out_size) {
    const float* x         = (const float*)d_in[0];
    const float* centroids = (const float*)d_in[1];
    const float* means     = (const float*)d_in[2];
    const float* log_stds  = (const float*)d_in[3];
    const float* logits    = (const float*)d_in[4];
    float* out = (float*)d_out;

    k0_prep   <<<E_N * K_N, 128>>>(centroids, means, log_stds, logits);
    k1_route  <<<B_N / 8,   256>>>(x, centroids);
    k2_scan   <<<1,          32>>>();
    k3_scatter<<<B_N / 256, 256>>>();
    k4_gemm   <<<B_N / TILE_M + E_N, 256>>>(x, out);
}

// round 4
// speedup vs baseline: 1.3192x; 1.3192x over previous
#include <cuda_runtime.h>
#include <cuda_bf16.h>
#include <cstdint>

// ============================================================================
// EinetMixture: route each row to nearest centroid (E=8), then compute only
// that expert's Gaussian-leaf log-likelihood (K=64 leaves) + logsumexp.
//
// leaf_ll[b,k] = sum_d ( a[e,k,d]*x^2 + b[e,k,d]*x ) + c[e,k]
// The d-reduction is a bf16 tensor-core GEMM with K-dim interleaved as
// (x[d], x^2[d]) pairs so each u32 MMA operand half-pair is one d.
// ============================================================================

#define B_N 32768
#define D_N 784
#define E_N 8
#define K_N 64
#define F4_PER_ROW 196        // 784/4

#define TILE_M 128
#define CHUNK_D 56            // d's per K4 mainloop chunk (784 = 14*56)
#define NCHUNK 14
#define KSTEPS 7              // k16 steps per chunk (8 d's each)
#define A_PITCH 60            // u32 pitch, %4==0 (16B stores)
#define B_PITCH 72            // u32 pitch, %4==0
#define C_PITCH 66            // float pitch for epilogue

#define LOG_2PI 1.8378770664093453f

// ---------------- device scratch (no allocation allowed) ----------------
__device__ uint32_t d_Wpack[E_N * D_N * K_N];   // [e][d][k] bf16x2 (bcoef, acoef)
__device__ float    d_ccomb[E_N * K_N];         // c + log_softmax(logits)
__device__ float    d_cnorm[E_N];
__device__ int      d_cluster[B_N];
__device__ int      d_counts[E_N];
__device__ int      d_offsets[E_N];
__device__ int      d_cursor[E_N];
__device__ int      d_tileStart[E_N + 1];
__device__ int      d_sortedIdx[B_N];

// ---------------- helpers ----------------
__device__ __forceinline__ uint32_t pack_x_x2(float v) {
    __nv_bfloat162 p = __floats2bfloat162_rn(v, v * v);   // lo = x, hi = x^2
    return *reinterpret_cast<uint32_t*>(&p);
}

__device__ __forceinline__ void mma_bf16(float* c, const uint32_t* a,
                                         uint32_t b0, uint32_t b1) {
    asm volatile(
        "mma.sync.aligned.m16n8k16.row.col.f32.bf16.bf16.f32 "
        "{%0,%1,%2,%3}, {%4,%5,%6,%7}, {%8,%9}, {%0,%1,%2,%3};\n"
        : "+f"(c[0]), "+f"(c[1]), "+f"(c[2]), "+f"(c[3])
        : "r"(a[0]), "r"(a[1]), "r"(a[2]), "r"(a[3]), "r"(b0), "r"(b1));
}

// ============================================================================
// K0: prep weights. grid = E*K CTAs of 128 threads; CTA handles one (e,k).
// ============================================================================
__global__ void __launch_bounds__(128) k0_prep(const float* __restrict__ centroids,
                                               const float* __restrict__ means,
                                               const float* __restrict__ log_stds,
                                               const float* __restrict__ logits) {
    int e = blockIdx.x >> 6;
    int k = blockIdx.x & 63;
    int tid = threadIdx.x;
    __shared__ float red[128];

    const float* mrow = means    + (size_t)(e * K_N + k) * D_N;
    const float* lrow = log_stds + (size_t)(e * K_N + k) * D_N;

    float csum = 0.f;
    for (int d = tid; d < D_N; d += 128) {
        float ls = lrow[d];
        float m  = mrow[d];
        float iv = expf(-2.f * ls);
        float ac = -0.5f * iv;        // coeff of x^2
        float bc = m * iv;            // coeff of x
        csum += -0.5f * m * m * iv - ls;
        __nv_bfloat162 p = __floats2bfloat162_rn(bc, ac);  // lo=b, hi=a
        d_Wpack[((e * D_N + d) << 6) + k] = *reinterpret_cast<uint32_t*>(&p);
    }
    red[tid] = csum;
    __syncthreads();
    for (int s = 64; s; s >>= 1) { if (tid < s) red[tid] += red[tid + s]; __syncthreads(); }
    if (tid == 0) {
        float ctot = red[0];
        const float* lg = logits + e * K_N;
        float mx = lg[0];
        for (int j = 1; j < K_N; j++) mx = fmaxf(mx, lg[j]);
        float s = 0.f;
        for (int j = 0; j < K_N; j++) s += expf(lg[j] - mx);
        float lse = mx + logf(s);
        d_ccomb[e * K_N + k] = ctot - 0.5f * (float)D_N * LOG_2PI + lg[k] - lse;
    }
    __syncthreads();

    if (k == 0) {   // centroid norms
        const float* crow = centroids + (size_t)e * D_N;
        float cn = 0.f;
        for (int d = tid; d < D_N; d += 128) { float c = crow[d]; cn += c * c; }
        red[tid] = cn;
        __syncthreads();
        for (int s = 64; s; s >>= 1) { if (tid < s) red[tid] += red[tid + s]; __syncthreads(); }
        if (tid == 0) d_cnorm[e] = red[0];
    }
    // zero per-replay counters (K0 runs before K1/K3 every replay)
    if (blockIdx.x == 0 && tid < E_N) { d_counts[tid] = 0; d_cursor[tid] = 0; }
}

// ============================================================================
// K1: routing. One warp per 4 rows (register-blocked -> centroid LDS / 4).
// argmin_e (||c_e||^2 - 2 x.c_e). Per-block histogram -> 8 global atomics.
// ============================================================================
__global__ void __launch_bounds__(256) k1_route(const float* __restrict__ x,
                                                const float* __restrict__ centroids) {
    __shared__ float4 cent[E_N * F4_PER_ROW];   // 25088 B
    __shared__ int hist[E_N];
    int tid = threadIdx.x;
    if (tid < E_N) hist[tid] = 0;
    const float4* c4 = reinterpret_cast<const float4*>(centroids);
    for (int j = tid; j < E_N * F4_PER_ROW; j += 256) cent[j] = c4[j];
    __syncthreads();

    int warp = tid >> 5, lane = tid & 31;
    int b0 = blockIdx.x * 32 + warp * 4;    // warp owns 4 consecutive rows
    const float4* x4 = reinterpret_cast<const float4*>(x) + (size_t)b0 * F4_PER_ROW;

    float dot[4][E_N];
#pragma unroll
    for (int r = 0; r < 4; r++)
#pragma unroll
        for (int e = 0; e < E_N; e++) dot[r][e] = 0.f;

    for (int j = lane; j < F4_PER_ROW; j += 32) {
        float4 xv[4];
#pragma unroll
        for (int r = 0; r < 4; r++) xv[r] = x4[(size_t)r * F4_PER_ROW + j];
#pragma unroll
        for (int e = 0; e < E_N; e++) {
            float4 cv = cent[e * F4_PER_ROW + j];
#pragma unroll
            for (int r = 0; r < 4; r++)
                dot[r][e] += xv[r].x * cv.x + xv[r].y * cv.y
                           + xv[r].z * cv.z + xv[r].w * cv.w;
        }
    }
#pragma unroll
    for (int r = 0; r < 4; r++)
#pragma unroll
        for (int e = 0; e < E_N; e++)
#pragma unroll
            for (int o = 16; o; o >>= 1)
                dot[r][e] += __shfl_xor_sync(0xffffffffu, dot[r][e], o);

    if (lane == 0) {
#pragma unroll
        for (int r = 0; r < 4; r++) {
            float best = 3.4e38f;
            int bi = 0;
#pragma unroll
            for (int e = 0; e < E_N; e++) {
                float s = d_cnorm[e] - 2.f * dot[r][e];
                if (s < best) { best = s; bi = e; }   // strict < => first-min == argmin
            }
            d_cluster[b0 + r] = bi;
            atomicAdd(&hist[bi], 1);                  // smem atomic
        }
    }
    __syncthreads();
    if (tid < E_N && hist[tid] > 0) atomicAdd(&d_counts[tid], hist[tid]);
}

// ============================================================================
// K2: exclusive scans (E=8, one thread).
// ============================================================================
__global__ void k2_scan() {
    if (threadIdx.x == 0 && blockIdx.x == 0) {
        int off = 0, ts = 0;
        for (int e = 0; e < E_N; e++) {
            d_offsets[e] = off;
            d_tileStart[e] = ts;
            int c = d_counts[e];
            off += c;
            ts += (c + TILE_M - 1) / TILE_M;
        }
        d_tileStart[E_N] = ts;
    }
}

// ============================================================================
// K3: counting-sort scatter. Block-local ranks via smem atomics; one global
// atomic per (block, expert) to reserve the segment.
// ============================================================================
__global__ void __launch_bounds__(256) k3_scatter() {
    __shared__ int sh_cnt[E_N];
    __shared__ int sh_base[E_N];
    int tid = threadIdx.x;
    if (tid < E_N) sh_cnt[tid] = 0;
    __syncthreads();
    int b = blockIdx.x * 256 + tid;
    int e = d_cluster[b];
    int p = atomicAdd(&sh_cnt[e], 1);       // block-local rank
    __syncthreads();
    if (tid < E_N)
        sh_base[tid] = sh_cnt[tid] ? atomicAdd(&d_cursor[tid], sh_cnt[tid]) : 0;
    __syncthreads();
    d_sortedIdx[d_offsets[e] + sh_base[e] + p] = b;
}

// ============================================================================
// K4: grouped GEMM, software-pipelined. CTA = 128 gathered rows of one
// expert x 64 leaves, K-dim = 1568 ((x,x^2) pairs), bf16 MMA fp32 accum.
// Chunk cb+1's global loads are issued in registers while chunk cb's MMAs run.
// ============================================================================
__global__ void __launch_bounds__(256) k4_gemm(const float* __restrict__ x,
                                               float* __restrict__ out) {
    __shared__ __align__(16) unsigned char raw[47616];
    uint32_t* As      = reinterpret_cast<uint32_t*>(raw);            // [128][A_PITCH]
    uint32_t* Bs      = reinterpret_cast<uint32_t*>(raw + 30720);    // [56][B_PITCH]
    int*      rowIdxS = reinterpret_cast<int*>(raw + 46848);         // [128]
    float*    ccombS  = reinterpret_cast<float*>(raw + 47360);       // [64]
    float*    Cs      = reinterpret_cast<float*>(raw);               // [128][C_PITCH] epilogue

    int t = blockIdx.x;
    if (t >= d_tileStart[E_N]) return;

    int e = 0;
#pragma unroll
    for (int i = 1; i < E_N; i++) if (t >= d_tileStart[i]) e = i;
    int rowbase = d_offsets[e] + (t - d_tileStart[e]) * TILE_M;
    int nrows = min(TILE_M, d_offsets[e] + d_counts[e] - rowbase);

    int tid = threadIdx.x;
    if (tid < TILE_M)
        rowIdxS[tid] = d_sortedIdx[rowbase + ((tid < nrows) ? tid : 0)];
    if (tid < K_N)
        ccombS[tid] = d_ccomb[e * K_N + tid];
    __syncthreads();

    const uint32_t* Wbase = d_Wpack + (size_t)e * (D_N * K_N);

    int warp = tid >> 5, lane = tid & 31;
    int g = lane >> 2, tig = lane & 3;

    float acc[8][4];
#pragma unroll
    for (int n = 0; n < 8; n++)
#pragma unroll
        for (int q = 0; q < 4; q++) acc[n][q] = 0.f;

    int r = tid >> 1, half = tid & 1;
    const float* xrow = x + (size_t)rowIdxS[r] * D_N;
    int mrow0 = warp * 16;

    // register staging buffers
    float4 xa[7];
    uint4  wb[4];

    // ---- prologue: load chunk 0 ----
#pragma unroll
    for (int q = 0; q < 7; q++)
        xa[q] = *reinterpret_cast<const float4*>(xrow + (half * 7 + q) * 4);
#pragma unroll
    for (int i = 0; i < 4; i++) {
        int j = tid + i * 256;
        if (j < CHUNK_D * K_N / 4) {
            int kk = j >> 4, nq = j & 15;
            wb[i] = *reinterpret_cast<const uint4*>(Wbase + (size_t)kk * K_N + nq * 4);
        }
    }

    for (int cb = 0; cb < NCHUNK; cb++) {
        // ---- store staged regs -> smem (convert A to (x,x^2) bf16 pairs) ----
#pragma unroll
        for (int q = 0; q < 7; q++) {
            int f4i = half * 7 + q;
            uint4 pk;
            pk.x = pack_x_x2(xa[q].x);
            pk.y = pack_x_x2(xa[q].y);
            pk.z = pack_x_x2(xa[q].z);
            pk.w = pack_x_x2(xa[q].w);
            *reinterpret_cast<uint4*>(&As[r * A_PITCH + f4i * 4]) = pk;
        }
#pragma unroll
        for (int i = 0; i < 4; i++) {
            int j = tid + i * 256;
            if (j < CHUNK_D * K_N / 4) {
                int kk = j >> 4, nq = j & 15;
                *reinterpret_cast<uint4*>(&Bs[kk * B_PITCH + nq * 4]) = wb[i];
            }
        }
        __syncthreads();

        // ---- issue next chunk's global loads (overlap with MMAs below) ----
        if (cb + 1 < NCHUNK) {
            int db = (cb + 1) * CHUNK_D;
#pragma unroll
            for (int q = 0; q < 7; q++)
                xa[q] = *reinterpret_cast<const float4*>(xrow + db + (half * 7 + q) * 4);
#pragma unroll
            for (int i = 0; i < 4; i++) {
                int j = tid + i * 256;
                if (j < CHUNK_D * K_N / 4) {
                    int kk = j >> 4, nq = j & 15;
                    wb[i] = *reinterpret_cast<const uint4*>(
                        Wbase + (size_t)(db + kk) * K_N + nq * 4);
                }
            }
        }

        // ---- MMA: warp: 16 rows x 64 cols (8 n8), 7 k16 steps ----
#pragma unroll
        for (int ks = 0; ks < KSTEPS; ks++) {
            int kkb = ks * 8;
            uint32_t a[4];
            a[0] = As[(mrow0 + g)     * A_PITCH + kkb + tig];
            a[1] = As[(mrow0 + 8 + g) * A_PITCH + kkb + tig];
            a[2] = As[(mrow0 + g)     * A_PITCH + kkb + tig + 4];
            a[3] = As[(mrow0 + 8 + g) * A_PITCH + kkb + tig + 4];
#pragma unroll
            for (int nt = 0; nt < 8; nt++) {
                uint32_t b0 = Bs[(kkb + tig)     * B_PITCH + nt * 8 + g];
                uint32_t b1 = Bs[(kkb + tig + 4) * B_PITCH + nt * 8 + g];
                mma_bf16(acc[nt], a, b0, b1);
            }
        }
        __syncthreads();
    }

    // ---- epilogue: accums -> smem (Cs aliases As/Bs; all MMA reads done) ----
    {
        int row0 = warp * 16 + g;
#pragma unroll
        for (int nt = 0; nt < 8; nt++) {
            int col = nt * 8 + tig * 2;
            Cs[row0 * C_PITCH + col]           = acc[nt][0];
            Cs[row0 * C_PITCH + col + 1]       = acc[nt][1];
            Cs[(row0 + 8) * C_PITCH + col]     = acc[nt][2];
            Cs[(row0 + 8) * C_PITCH + col + 1] = acc[nt][3];
        }
    }
    __syncthreads();

    // ---- logsumexp per row, scatter to original index ----
    if (tid < TILE_M) {
        const float* crow = &Cs[tid * C_PITCH];
        float mx = -3.4e38f;
#pragma unroll 8
        for (int j = 0; j < K_N; j++) mx = fmaxf(mx, crow[j] + ccombS[j]);
        float s = 0.f;
#pragma unroll 8
        for (int j = 0; j < K_N; j++) s += expf(crow[j] + ccombS[j] - mx);
        float ll = mx + logf(s);
        if (tid < nrows) out[rowIdxS[tid]] = ll;
    }
}

// ============================================================================
extern "C" void kernel_launch(void* const* d_in, const int* in_sizes, int n_in,
                              void* d_out, int out_size) {
    const float* x         = (const float*)d_in[0];
    const float* centroids = (const float*)d_in[1];
    const float* means     = (const float*)d_in[2];
    const float* log_stds  = (const float*)d_in[3];
    const float* logits    = (const float*)d_in[4];
    float* out = (float*)d_out;

    k0_prep   <<<E_N * K_N, 128>>>(centroids, means, log_stds, logits);
    k1_route  <<<B_N / 32,  256>>>(x, centroids);
    k2_scan   <<<1,          32>>>();
    k3_scatter<<<B_N / 256, 256>>>();
    k4_gemm   <<<B_N / TILE_M + E_N, 256>>>(x, out);
}

// round 5
// speedup vs baseline: 1.3924x; 1.0555x over previous
#include <cuda_runtime.h>
#include <cuda_bf16.h>
#include <cstdint>

// ============================================================================
// EinetMixture: route each row to nearest centroid (E=8), then compute only
// that expert's Gaussian-leaf log-likelihood (K=64 leaves) + logsumexp.
//
// leaf_ll[b,k] = sum_d ( a[e,k,d]*x^2 + b[e,k,d]*x ) + c[e,k]
// The d-reduction is a bf16 tensor-core GEMM with K-dim interleaved as
// (x[d], x^2[d]) pairs so each u32 MMA operand half-pair is one d.
//
// Launches: k0 prep -> k1 route -> k3 scatter -> k4 grouped GEMM.
// (scan of the 8 counts is recomputed in-kernel; no k2.)
// ============================================================================

#define B_N 32768
#define D_N 784
#define E_N 8
#define K_N 64
#define F4_PER_ROW 196        // 784/4

#define TILE_M 128
#define CHUNK_D 56            // d's per K4 mainloop chunk (784 = 14*56)
#define NCHUNK 14
#define KSTEPS 7              // k16 steps per chunk (8 d's each)
#define A_PITCH 60            // u32 pitch (conflict-free A frags, %4==0)
#define B_PITCH 72            // u32 pitch (conflict-free B frags, %4==0)
#define C_PITCH 66            // float pitch for epilogue

#define A_BUF_BYTES (TILE_M * A_PITCH * 4)      // 30720
#define B_BUF_BYTES (CHUNK_D * B_PITCH * 4)     // 16128
#define SMEM_B_OFF  (2 * A_BUF_BYTES)           // 61440
#define SMEM_IDX_OFF (SMEM_B_OFF + 2 * B_BUF_BYTES)   // 93696
#define SMEM_CC_OFF  (SMEM_IDX_OFF + TILE_M * 4)      // 94208
#define SMEM_TOTAL_K4 (SMEM_CC_OFF + K_N * 4)         // 94464

#define LOG_2PI 1.8378770664093453f

// ---------------- device scratch (no allocation allowed) ----------------
__device__ __align__(16) uint32_t d_Wpack[E_N * D_N * K_N]; // [e][d][k] bf16x2 (b,a)
__device__ float    d_ccomb[E_N * K_N];         // c + log_softmax(logits)
__device__ float    d_cnorm[E_N];
__device__ int      d_cluster[B_N];
__device__ int      d_counts[E_N];
__device__ int      d_cursor[E_N];
__device__ int      d_sortedIdx[B_N];

// ---------------- helpers ----------------
__device__ __forceinline__ uint32_t pack_x_x2(float v) {
    __nv_bfloat162 p = __floats2bfloat162_rn(v, v * v);   // lo = x, hi = x^2
    return *reinterpret_cast<uint32_t*>(&p);
}

__device__ __forceinline__ void mma_bf16(float* c, const uint32_t* a,
                                         uint32_t b0, uint32_t b1) {
    asm volatile(
        "mma.sync.aligned.m16n8k16.row.col.f32.bf16.bf16.f32 "
        "{%0,%1,%2,%3}, {%4,%5,%6,%7}, {%8,%9}, {%0,%1,%2,%3};\n"
        : "+f"(c[0]), "+f"(c[1]), "+f"(c[2]), "+f"(c[3])
        : "r"(a[0]), "r"(a[1]), "r"(a[2]), "r"(a[3]), "r"(b0), "r"(b1));
}

__device__ __forceinline__ void cp_async16(uint32_t smem_addr, const void* gptr) {
    asm volatile("cp.async.cg.shared.global [%0], [%1], 16;\n"
                 :: "r"(smem_addr), "l"(gptr));
}
#define CP_COMMIT() asm volatile("cp.async.commit_group;\n" ::: "memory")
#define CP_WAIT0()  asm volatile("cp.async.wait_group 0;\n" ::: "memory")

// ============================================================================
// K0: prep weights. grid = E*K CTAs of 128 threads; CTA handles one (e,k).
// ============================================================================
__global__ void __launch_bounds__(128) k0_prep(const float* __restrict__ centroids,
                                               const float* __restrict__ means,
                                               const float* __restrict__ log_stds,
                                               const float* __restrict__ logits) {
    int e = blockIdx.x >> 6;
    int k = blockIdx.x & 63;
    int tid = threadIdx.x;
    __shared__ float red[128];

    const float* mrow = means    + (size_t)(e * K_N + k) * D_N;
    const float* lrow = log_stds + (size_t)(e * K_N + k) * D_N;

    float csum = 0.f;
    for (int d = tid; d < D_N; d += 128) {
        float ls = lrow[d];
        float m  = mrow[d];
        float iv = expf(-2.f * ls);
        float ac = -0.5f * iv;        // coeff of x^2
        float bc = m * iv;            // coeff of x
        csum += -0.5f * m * m * iv - ls;
        __nv_bfloat162 p = __floats2bfloat162_rn(bc, ac);  // lo=b, hi=a
        d_Wpack[((e * D_N + d) << 6) + k] = *reinterpret_cast<uint32_t*>(&p);
    }
    red[tid] = csum;
    __syncthreads();
    for (int s = 64; s; s >>= 1) { if (tid < s) red[tid] += red[tid + s]; __syncthreads(); }
    if (tid == 0) {
        float ctot = red[0];
        const float* lg = logits + e * K_N;
        float mx = lg[0];
        for (int j = 1; j < K_N; j++) mx = fmaxf(mx, lg[j]);
        float s = 0.f;
        for (int j = 0; j < K_N; j++) s += expf(lg[j] - mx);
        float lse = mx + logf(s);
        d_ccomb[e * K_N + k] = ctot - 0.5f * (float)D_N * LOG_2PI + lg[k] - lse;
    }
    __syncthreads();

    if (k == 0) {   // centroid norms
        const float* crow = centroids + (size_t)e * D_N;
        float cn = 0.f;
        for (int d = tid; d < D_N; d += 128) { float c = crow[d]; cn += c * c; }
        red[tid] = cn;
        __syncthreads();
        for (int s = 64; s; s >>= 1) { if (tid < s) red[tid] += red[tid + s]; __syncthreads(); }
        if (tid == 0) d_cnorm[e] = red[0];
    }
    // zero per-replay counters (K0 runs first every replay)
    if (blockIdx.x == 0 && tid < E_N) { d_counts[tid] = 0; d_cursor[tid] = 0; }
}

// ============================================================================
// K1: routing. One warp per 4 rows (register-blocked); centroids in smem.
// argmin_e (||c_e||^2 - 2 x.c_e). Per-block histogram -> 8 global atomics.
// ============================================================================
__global__ void __launch_bounds__(256) k1_route(const float* __restrict__ x,
                                                const float* __restrict__ centroids) {
    __shared__ float4 cent[E_N * F4_PER_ROW];   // 25088 B
    __shared__ int hist[E_N];
    int tid = threadIdx.x;
    if (tid < E_N) hist[tid] = 0;
    const float4* c4 = reinterpret_cast<const float4*>(centroids);
    for (int j = tid; j < E_N * F4_PER_ROW; j += 256) cent[j] = c4[j];
    __syncthreads();

    int warp = tid >> 5, lane = tid & 31;
    int b0 = blockIdx.x * 32 + warp * 4;    // warp owns 4 consecutive rows
    const float4* x4 = reinterpret_cast<const float4*>(x) + (size_t)b0 * F4_PER_ROW;

    float dot[4][E_N];
#pragma unroll
    for (int r = 0; r < 4; r++)
#pragma unroll
        for (int e = 0; e < E_N; e++) dot[r][e] = 0.f;

    for (int j = lane; j < F4_PER_ROW; j += 32) {
        float4 xv[4];
#pragma unroll
        for (int r = 0; r < 4; r++) xv[r] = x4[(size_t)r * F4_PER_ROW + j];
#pragma unroll
        for (int e = 0; e < E_N; e++) {
            float4 cv = cent[e * F4_PER_ROW + j];
#pragma unroll
            for (int r = 0; r < 4; r++)
                dot[r][e] += xv[r].x * cv.x + xv[r].y * cv.y
                           + xv[r].z * cv.z + xv[r].w * cv.w;
        }
    }
#pragma unroll
    for (int r = 0; r < 4; r++)
#pragma unroll
        for (int e = 0; e < E_N; e++)
#pragma unroll
            for (int o = 16; o; o >>= 1)
                dot[r][e] += __shfl_xor_sync(0xffffffffu, dot[r][e], o);

    if (lane == 0) {
#pragma unroll
        for (int r = 0; r < 4; r++) {
            float best = 3.4e38f;
            int bi = 0;
#pragma unroll
            for (int e = 0; e < E_N; e++) {
                float s = d_cnorm[e] - 2.f * dot[r][e];
                if (s < best) { best = s; bi = e; }   // strict < => first-min == argmin
            }
            d_cluster[b0 + r] = bi;
            atomicAdd(&hist[bi], 1);                  // smem atomic
        }
    }
    __syncthreads();
    if (tid < E_N && hist[tid] > 0) atomicAdd(&d_counts[tid], hist[tid]);
}

// ============================================================================
// K3: counting-sort scatter. Per-block offsets-scan (E=8, thread 0), smem
// ranks, one global atomic per (block, expert).
// ============================================================================
__global__ void __launch_bounds__(256) k3_scatter() {
    __shared__ int sh_cnt[E_N];
    __shared__ int sh_base[E_N];
    __shared__ int sh_off[E_N];
    int tid = threadIdx.x;
    if (tid < E_N) sh_cnt[tid] = 0;
    if (tid == 0) {          // exclusive scan of counts (8 values)
        int off = 0;
#pragma unroll
        for (int e = 0; e < E_N; e++) { sh_off[e] = off; off += d_counts[e]; }
    }
    __syncthreads();
    int b = blockIdx.x * 256 + tid;
    int e = d_cluster[b];
    int p = atomicAdd(&sh_cnt[e], 1);       // block-local rank
    __syncthreads();
    if (tid < E_N)
        sh_base[tid] = sh_cnt[tid] ? atomicAdd(&d_cursor[tid], sh_cnt[tid]) : 0;
    __syncthreads();
    d_sortedIdx[sh_off[e] + sh_base[e] + p] = b;
}

// ============================================================================
// K4: grouped GEMM, double-buffered, ONE __syncthreads per chunk.
// CTA = 128 gathered rows of one expert x 64 leaves, K-dim = 1568.
// B tile via cp.async (global->smem), A via reg staging (needs f32->bf16x2).
// Hazards: store A_i -> As[i&1] races MMA_{i-2} (done by sync_{i-1});
// cp.async B_{i+1} -> Bs[(i+1)&1] races MMA_{i-1} (done by sync_i).
// ============================================================================
__global__ void __launch_bounds__(256) k4_gemm(const float* __restrict__ x,
                                               float* __restrict__ out) {
    extern __shared__ __align__(16) unsigned char raw[];
    int*      rowIdxS = reinterpret_cast<int*>(raw + SMEM_IDX_OFF);
    float*    ccombS  = reinterpret_cast<float*>(raw + SMEM_CC_OFF);
    float*    Cs      = reinterpret_cast<float*>(raw);   // epilogue, aliases As

    int tid = threadIdx.x;
    int t = blockIdx.x;

    // per-block scan of d_counts (E=8): find expert e, tile index, row offset
    int e = -1, tileIn = 0, offE = 0, nrows = 0;
    {
        int ts = 0, off = 0;
#pragma unroll
        for (int i = 0; i < E_N; i++) {
            int c = d_counts[i];
            int tiles = (c + TILE_M - 1) >> 7;
            if (e < 0 && t >= ts && t < ts + tiles) {
                e = i; tileIn = t - ts; offE = off;
                nrows = min(TILE_M, c - tileIn * TILE_M);
            }
            ts += tiles; off += c;
        }
        if (e < 0) return;   // beyond last tile
    }
    int rowbase = offE + tileIn * TILE_M;

    if (tid < TILE_M)
        rowIdxS[tid] = d_sortedIdx[rowbase + ((tid < nrows) ? tid : 0)];
    if (tid < K_N)
        ccombS[tid] = d_ccomb[e * K_N + tid];
    __syncthreads();

    const uint32_t* Wbase = d_Wpack + (size_t)e * (D_N * K_N);
    uint32_t smem_u32 = (uint32_t)__cvta_generic_to_shared(raw);

    int warp = tid >> 5, lane = tid & 31;
    int g = lane >> 2, tig = lane & 3;

    float acc[8][4];
#pragma unroll
    for (int n = 0; n < 8; n++)
#pragma unroll
        for (int q = 0; q < 4; q++) acc[n][q] = 0.f;

    int r = tid >> 1, half = tid & 1;
    const float* xrow = x + (size_t)rowIdxS[r] * D_N;
    int mrow0 = warp * 16;

    float4 xa[7];        // A register staging (one chunk ahead)

    // cp.async B chunk -> buffer bb
    auto issueB = [&](int cb, int bb) {
        uint32_t bdst = smem_u32 + SMEM_B_OFF + bb * B_BUF_BYTES;
        const uint32_t* src = Wbase + (size_t)cb * CHUNK_D * K_N;
#pragma unroll
        for (int i = 0; i < 4; i++) {
            int j = tid + i * 256;
            if (j < CHUNK_D * K_N / 4) {
                int kk = j >> 4, nq = j & 15;
                cp_async16(bdst + (kk * B_PITCH + nq * 4) * 4,
                           src + (size_t)kk * K_N + nq * 4);
            }
        }
    };

    // ---- prologue ----
#pragma unroll
    for (int q = 0; q < 7; q++)
        xa[q] = *reinterpret_cast<const float4*>(xrow + (half * 7 + q) * 4);
    issueB(0, 0);
    CP_COMMIT();

    for (int cb = 0; cb < NCHUNK; cb++) {
        int buf = cb & 1;
        uint32_t* As = reinterpret_cast<uint32_t*>(raw + buf * A_BUF_BYTES);
        uint32_t* Bs = reinterpret_cast<uint32_t*>(raw + SMEM_B_OFF + buf * B_BUF_BYTES);

        // store staged A regs -> As[buf] (safe: MMA_{cb-2} done by sync_{cb-1})
#pragma unroll
        for (int q = 0; q < 7; q++) {
            int f4i = half * 7 + q;
            uint4 pk;
            pk.x = pack_x_x2(xa[q].x);
            pk.y = pack_x_x2(xa[q].y);
            pk.z = pack_x_x2(xa[q].z);
            pk.w = pack_x_x2(xa[q].w);
            *reinterpret_cast<uint4*>(&As[r * A_PITCH + f4i * 4]) = pk;
        }
        CP_WAIT0();          // Bs[buf] landed
        __syncthreads();     // As[buf] + Bs[buf] visible; MMA_{cb-1} finished

        if (cb + 1 < NCHUNK) {
            int db = (cb + 1) * CHUNK_D;
#pragma unroll
            for (int q = 0; q < 7; q++)
                xa[q] = *reinterpret_cast<const float4*>(xrow + db + (half * 7 + q) * 4);
            issueB(cb + 1, buf ^ 1);    // safe: MMA_{cb-1} done by this sync
            CP_COMMIT();
        }

        // ---- MMA: warp: 16 rows x 64 cols (8 n8), 7 k16 steps ----
#pragma unroll
        for (int ks = 0; ks < KSTEPS; ks++) {
            int kkb = ks * 8;
            uint32_t a[4];
            a[0] = As[(mrow0 + g)     * A_PITCH + kkb + tig];
            a[1] = As[(mrow0 + 8 + g) * A_PITCH + kkb + tig];
            a[2] = As[(mrow0 + g)     * A_PITCH + kkb + tig + 4];
            a[3] = As[(mrow0 + 8 + g) * A_PITCH + kkb + tig + 4];
#pragma unroll
            for (int nt = 0; nt < 8; nt++) {
                uint32_t b0 = Bs[(kkb + tig)     * B_PITCH + nt * 8 + g];
                uint32_t b1 = Bs[(kkb + tig + 4) * B_PITCH + nt * 8 + g];
                mma_bf16(acc[nt], a, b0, b1);
            }
        }
    }
    __syncthreads();   // all MMAs done before Cs aliases the A buffers

    // ---- epilogue: accums -> smem ----
    {
        int row0 = warp * 16 + g;
#pragma unroll
        for (int nt = 0; nt < 8; nt++) {
            int col = nt * 8 + tig * 2;
            Cs[row0 * C_PITCH + col]           = acc[nt][0];
            Cs[row0 * C_PITCH + col + 1]       = acc[nt][1];
            Cs[(row0 + 8) * C_PITCH + col]     = acc[nt][2];
            Cs[(row0 + 8) * C_PITCH + col + 1] = acc[nt][3];
        }
    }
    __syncthreads();

    // ---- logsumexp per row, scatter to original index ----
    if (tid < TILE_M) {
        const float* crow = &Cs[tid * C_PITCH];
        float mx = -3.4e38f;
#pragma unroll 8
        for (int j = 0; j < K_N; j++) mx = fmaxf(mx, crow[j] + ccombS[j]);
        float s = 0.f;
#pragma unroll 8
        for (int j = 0; j < K_N; j++) s += expf(crow[j] + ccombS[j] - mx);
        float ll = mx + logf(s);
        if (tid < nrows) out[rowIdxS[tid]] = ll;
    }
}

// ============================================================================
extern "C" void kernel_launch(void* const* d_in, const int* in_sizes, int n_in,
                              void* d_out, int out_size) {
    const float* x         = (const float*)d_in[0];
    const float* centroids = (const float*)d_in[1];
    const float* means     = (const float*)d_in[2];
    const float* log_stds  = (const float*)d_in[3];
    const float* logits    = (const float*)d_in[4];
    float* out = (float*)d_out;

    static bool attr_set = false;
    if (!attr_set) {
        cudaFuncSetAttribute(k4_gemm, cudaFuncAttributeMaxDynamicSharedMemorySize,
                             SMEM_TOTAL_K4);
        attr_set = true;
    }

    k0_prep   <<<E_N * K_N, 128>>>(centroids, means, log_stds, logits);
    k1_route  <<<B_N / 32,  256>>>(x, centroids);
    k3_scatter<<<B_N / 256, 256>>>();
    k4_gemm   <<<B_N / TILE_M + E_N, 256, SMEM_TOTAL_K4>>>(x, out);
}

// round 7
// speedup vs baseline: 1.4812x; 1.0638x over previous
#include <cuda_runtime.h>
#include <cuda_bf16.h>
#include <cstdint>

// ============================================================================
// EinetMixture: route each row to nearest centroid (E=8), then compute only
// that expert's Gaussian-leaf log-likelihood (K=64 leaves) + logsumexp.
//
// leaf_ll[b,k] = sum_d ( a[e,k,d]*x^2 + b[e,k,d]*x ) + c[e,k]
// d-reduction = bf16 mma.sync GEMM; K-dim interleaved as (x[d], x^2[d]) pairs
// matching W pairs (bcoef, acoef). (tcgen05 unavailable: bench targets sm_100.)
//
// Launches: k0 prep -> k1 route -> k3 scatter -> k4 grouped GEMM.
// ============================================================================

#define B_N 32768
#define D_N 784
#define D_PAD 800             // 25 chunks of 32 d (pad coeffs are zero)
#define E_N 8
#define K_N 64
#define F4_PER_ROW 196        // 784/4

#define TILE_M 128
#define CHUNK_D 32            // d's per K4 chunk (64 bf16 of K)
#define NCHUNK 25
#define KSTEPS 4              // k16 steps per chunk
#define A_PITCH 36            // u32 pitch; banks (4g+tig) distinct
#define B_PITCH 72            // u32 pitch; banks (8tig+g) distinct
#define C_PITCH 66            // float pitch for epilogue

#define A_BUF_BYTES (TILE_M * A_PITCH * 4)      // 18432
#define B_BUF_BYTES (CHUNK_D * B_PITCH * 4)     // 9216
#define SM_B_OFF   (2 * A_BUF_BYTES)            // 36864
#define SM_IDX_OFF (SM_B_OFF + 2 * B_BUF_BYTES) // 55296
#define SM_CC_OFF  (SM_IDX_OFF + TILE_M * 4)    // 55808
#define SM_TOTAL_K4 (SM_CC_OFF + K_N * 4)       // 56064

#define LOG_2PI 1.8378770664093453f

// ---------------- device scratch (no allocation allowed) ----------------
__device__ __align__(16) uint32_t d_Wpack[E_N * D_PAD * K_N]; // [e][d][k] bf16x2 (b,a)
__device__ float    d_ccomb[E_N * K_N];         // c + log_softmax(logits)
__device__ float    d_cnorm[E_N];
__device__ int      d_cluster[B_N];
__device__ int      d_counts[E_N];
__device__ int      d_cursor[E_N];
__device__ int      d_sortedIdx[B_N];

// ---------------- helpers ----------------
__device__ __forceinline__ uint32_t pack_x_x2(float v) {
    __nv_bfloat162 p = __floats2bfloat162_rn(v, v * v);   // lo = x, hi = x^2
    return *reinterpret_cast<uint32_t*>(&p);
}

__device__ __forceinline__ void mma_bf16(float* c, const uint32_t* a,
                                         uint32_t b0, uint32_t b1) {
    asm volatile(
        "mma.sync.aligned.m16n8k16.row.col.f32.bf16.bf16.f32 "
        "{%0,%1,%2,%3}, {%4,%5,%6,%7}, {%8,%9}, {%0,%1,%2,%3};\n"
        : "+f"(c[0]), "+f"(c[1]), "+f"(c[2]), "+f"(c[3])
        : "r"(a[0]), "r"(a[1]), "r"(a[2]), "r"(a[3]), "r"(b0), "r"(b1));
}

__device__ __forceinline__ void cp_async16(uint32_t smem_addr, const void* gptr) {
    asm volatile("cp.async.cg.shared.global [%0], [%1], 16;\n"
                 :: "r"(smem_addr), "l"(gptr));
}
#define CP_COMMIT() asm volatile("cp.async.commit_group;\n" ::: "memory")
#define CP_WAIT0()  asm volatile("cp.async.wait_group 0;\n" ::: "memory")

// ============================================================================
// K0: prep weights. grid = E*K CTAs of 128 threads; CTA handles one (e,k).
// W padded to D_PAD with zeros so K4's last chunk adds exactly 0.
// ============================================================================
__global__ void __launch_bounds__(128) k0_prep(const float* __restrict__ centroids,
                                               const float* __restrict__ means,
                                               const float* __restrict__ log_stds,
                                               const float* __restrict__ logits) {
    int e = blockIdx.x >> 6;
    int k = blockIdx.x & 63;
    int tid = threadIdx.x;
    __shared__ float red[128];

    const float* mrow = means    + (size_t)(e * K_N + k) * D_N;
    const float* lrow = log_stds + (size_t)(e * K_N + k) * D_N;

    float csum = 0.f;
    for (int d = tid; d < D_PAD; d += 128) {
        uint32_t pk = 0;
        if (d < D_N) {
            float ls = lrow[d];
            float m  = mrow[d];
            float iv = expf(-2.f * ls);
            float ac = -0.5f * iv;        // coeff of x^2
            float bc = m * iv;            // coeff of x
            csum += -0.5f * m * m * iv - ls;
            __nv_bfloat162 p = __floats2bfloat162_rn(bc, ac);  // lo=b, hi=a
            pk = *reinterpret_cast<uint32_t*>(&p);
        }
        d_Wpack[((e * D_PAD + d) << 6) + k] = pk;
    }
    red[tid] = csum;
    __syncthreads();
    for (int s = 64; s; s >>= 1) { if (tid < s) red[tid] += red[tid + s]; __syncthreads(); }
    if (tid == 0) {
        float ctot = red[0];
        const float* lg = logits + e * K_N;
        float mx = lg[0];
        for (int j = 1; j < K_N; j++) mx = fmaxf(mx, lg[j]);
        float s = 0.f;
        for (int j = 0; j < K_N; j++) s += expf(lg[j] - mx);
        float lse = mx + logf(s);
        d_ccomb[e * K_N + k] = ctot - 0.5f * (float)D_N * LOG_2PI + lg[k] - lse;
    }
    __syncthreads();

    if (k == 0) {   // centroid norms
        const float* crow = centroids + (size_t)e * D_N;
        float cn = 0.f;
        for (int d = tid; d < D_N; d += 128) { float c = crow[d]; cn += c * c; }
        red[tid] = cn;
        __syncthreads();
        for (int s = 64; s; s >>= 1) { if (tid < s) red[tid] += red[tid + s]; __syncthreads(); }
        if (tid == 0) d_cnorm[e] = red[0];
    }
    if (blockIdx.x == 0 && tid < E_N) { d_counts[tid] = 0; d_cursor[tid] = 0; }
}

// ============================================================================
// K1: routing. One warp per 4 rows (register-blocked); centroids in smem.
// argmin_e (||c_e||^2 - 2 x.c_e). Per-block histogram -> 8 global atomics.
// ============================================================================
__global__ void __launch_bounds__(256) k1_route(const float* __restrict__ x,
                                                const float* __restrict__ centroids) {
    __shared__ float4 cent[E_N * F4_PER_ROW];   // 25088 B
    __shared__ int hist[E_N];
    int tid = threadIdx.x;
    if (tid < E_N) hist[tid] = 0;
    const float4* c4 = reinterpret_cast<const float4*>(centroids);
    for (int j = tid; j < E_N * F4_PER_ROW; j += 256) cent[j] = c4[j];
    __syncthreads();

    int warp = tid >> 5, lane = tid & 31;
    int b0 = blockIdx.x * 32 + warp * 4;
    const float4* x4 = reinterpret_cast<const float4*>(x) + (size_t)b0 * F4_PER_ROW;

    float dot[4][E_N];
#pragma unroll
    for (int r = 0; r < 4; r++)
#pragma unroll
        for (int e = 0; e < E_N; e++) dot[r][e] = 0.f;

    for (int j = lane; j < F4_PER_ROW; j += 32) {
        float4 xv[4];
#pragma unroll
        for (int r = 0; r < 4; r++) xv[r] = x4[(size_t)r * F4_PER_ROW + j];
#pragma unroll
        for (int e = 0; e < E_N; e++) {
            float4 cv = cent[e * F4_PER_ROW + j];
#pragma unroll
            for (int r = 0; r < 4; r++)
                dot[r][e] += xv[r].x * cv.x + xv[r].y * cv.y
                           + xv[r].z * cv.z + xv[r].w * cv.w;
        }
    }
#pragma unroll
    for (int r = 0; r < 4; r++)
#pragma unroll
        for (int e = 0; e < E_N; e++)
#pragma unroll
            for (int o = 16; o; o >>= 1)
                dot[r][e] += __shfl_xor_sync(0xffffffffu, dot[r][e], o);

    if (lane == 0) {
#pragma unroll
        for (int r = 0; r < 4; r++) {
            float best = 3.4e38f;
            int bi = 0;
#pragma unroll
            for (int e = 0; e < E_N; e++) {
                float s = d_cnorm[e] - 2.f * dot[r][e];
                if (s < best) { best = s; bi = e; }   // first-min == argmin
            }
            d_cluster[b0 + r] = bi;
            atomicAdd(&hist[bi], 1);
        }
    }
    __syncthreads();
    if (tid < E_N && hist[tid] > 0) atomicAdd(&d_counts[tid], hist[tid]);
}

// ============================================================================
// K3: counting-sort scatter. Block-local ranks; 8 global atomics per block.
// ============================================================================
__global__ void __launch_bounds__(256) k3_scatter() {
    __shared__ int sh_cnt[E_N];
    __shared__ int sh_base[E_N];
    __shared__ int sh_off[E_N];
    int tid = threadIdx.x;
    if (tid < E_N) sh_cnt[tid] = 0;
    if (tid == 0) {
        int off = 0;
#pragma unroll
        for (int e = 0; e < E_N; e++) { sh_off[e] = off; off += d_counts[e]; }
    }
    __syncthreads();
    int b = blockIdx.x * 256 + tid;
    int e = d_cluster[b];
    int p = atomicAdd(&sh_cnt[e], 1);
    __syncthreads();
    if (tid < E_N)
        sh_base[tid] = sh_cnt[tid] ? atomicAdd(&d_cursor[tid], sh_cnt[tid]) : 0;
    __syncthreads();
    d_sortedIdx[sh_off[e] + sh_base[e] + p] = b;
}

// ============================================================================
// K4: grouped GEMM, 512 threads (16 warps), double-buffered, one sync/chunk.
// CTA = 128 gathered rows of one expert x 64 leaves, 25 chunks of 32 d.
// Warp (mw = warp>>1, nw = warp&1) owns rows [mw*16,+16) x cols [nw*32,+32):
// acc[4][4] (16 regs). A reg-staged (8 regs) + STS; B via cp.async of W.
// Hazards identical to R5's argument (A store vs MMA_{cb-2}; B vs MMA_{cb-1}).
// ============================================================================
__global__ void __launch_bounds__(512, 2) k4_gemm(const float* __restrict__ x,
                                                  float* __restrict__ out) {
    extern __shared__ __align__(16) unsigned char raw[];
    int*   rowIdxS = reinterpret_cast<int*>(raw + SM_IDX_OFF);
    float* ccombS  = reinterpret_cast<float*>(raw + SM_CC_OFF);
    float* Cs      = reinterpret_cast<float*>(raw);   // epilogue, aliases A bufs

    int tid = threadIdx.x;
    int t = blockIdx.x;

    // find (expert, tile) from d_counts
    int e = -1, tileIn = 0, offE = 0, nrows = 0;
    {
        int ts = 0, off = 0;
#pragma unroll
        for (int i = 0; i < E_N; i++) {
            int c = d_counts[i];
            int tiles = (c + TILE_M - 1) >> 7;
            if (e < 0 && t >= ts && t < ts + tiles) {
                e = i; tileIn = t - ts; offE = off;
                nrows = min(TILE_M, c - tileIn * TILE_M);
            }
            ts += tiles; off += c;
        }
        if (e < 0) return;
    }
    int rowbase = offE + tileIn * TILE_M;

    if (tid < TILE_M)
        rowIdxS[tid] = d_sortedIdx[rowbase + ((tid < nrows) ? tid : 0)];
    if (tid < K_N)
        ccombS[tid] = d_ccomb[e * K_N + tid];
    __syncthreads();

    const uint32_t* WbE = d_Wpack + (size_t)e * (D_PAD * K_N);
    uint32_t smem_u32 = (uint32_t)__cvta_generic_to_shared(raw);

    int warp = tid >> 5, lane = tid & 31;
    int g = lane >> 2, tig = lane & 3;
    int mw = warp >> 1, nw = warp & 1;
    int mrow0 = mw * 16, n0 = nw * 32;

    float acc[4][4];
#pragma unroll
    for (int n = 0; n < 4; n++)
#pragma unroll
        for (int q = 0; q < 4; q++) acc[n][q] = 0.f;

    int r = tid >> 2, quarter = tid & 3;       // 4 threads per A row
    const float* xrow = x + (size_t)rowIdxS[r] * D_N;

    uint4 sa[2];   // staged packed A (8 d per thread)

    auto stageA = [&](int cb) {
#pragma unroll
        for (int s = 0; s < 2; s++) {
            int d = cb * CHUNK_D + quarter * 8 + s * 4;
            if (d < D_N) {
                float4 v = *reinterpret_cast<const float4*>(xrow + d);
                sa[s].x = pack_x_x2(v.x); sa[s].y = pack_x_x2(v.y);
                sa[s].z = pack_x_x2(v.z); sa[s].w = pack_x_x2(v.w);
            } else {
                sa[s].x = sa[s].y = sa[s].z = sa[s].w = 0u;
            }
        }
    };
    auto issueB = [&](int cb, int buf) {
        uint32_t bdst = smem_u32 + SM_B_OFF + buf * B_BUF_BYTES;
        int kk = tid >> 4, n4 = (tid & 15) * 4;
        cp_async16(bdst + (kk * B_PITCH + n4) * 4,
                   WbE + (size_t)cb * (CHUNK_D * K_N) + tid * 4);
    };

    // ---- prologue ----
    stageA(0);
    issueB(0, 0);
    CP_COMMIT();

    for (int cb = 0; cb < NCHUNK; cb++) {
        int buf = cb & 1;
        uint32_t* As = reinterpret_cast<uint32_t*>(raw + buf * A_BUF_BYTES);
        uint32_t* Bs = reinterpret_cast<uint32_t*>(raw + SM_B_OFF + buf * B_BUF_BYTES);

        // store staged A -> As[buf] (MMA_{cb-2} done by sync_{cb-1})
#pragma unroll
        for (int s = 0; s < 2; s++)
            *reinterpret_cast<uint4*>(&As[r * A_PITCH + quarter * 8 + s * 4]) = sa[s];
        CP_WAIT0();          // Bs[buf] landed
        __syncthreads();     // tiles visible; MMA_{cb-1} finished everywhere

        if (cb + 1 < NCHUNK) {
            stageA(cb + 1);
            issueB(cb + 1, buf ^ 1);   // safe: MMA_{cb-1} done by this sync
            CP_COMMIT();
        }

        // ---- MMA: 16 rows x 32 cols, 4 k16 steps ----
#pragma unroll
        for (int ks = 0; ks < KSTEPS; ks++) {
            int kkb = ks * 8;
            uint32_t a[4];
            a[0] = As[(mrow0 + g)     * A_PITCH + kkb + tig];
            a[1] = As[(mrow0 + 8 + g) * A_PITCH + kkb + tig];
            a[2] = As[(mrow0 + g)     * A_PITCH + kkb + tig + 4];
            a[3] = As[(mrow0 + 8 + g) * A_PITCH + kkb + tig + 4];
#pragma unroll
            for (int nt = 0; nt < 4; nt++) {
                uint32_t b0 = Bs[(kkb + tig)     * B_PITCH + n0 + nt * 8 + g];
                uint32_t b1 = Bs[(kkb + tig + 4) * B_PITCH + n0 + nt * 8 + g];
                mma_bf16(acc[nt], a, b0, b1);
            }
        }
    }
    __syncthreads();   // all MMAs done before Cs aliases the A buffers

    // ---- epilogue: accums -> smem ----
    {
        int row0 = mrow0 + g;
#pragma unroll
        for (int nt = 0; nt < 4; nt++) {
            int col = n0 + nt * 8 + tig * 2;
            Cs[row0 * C_PITCH + col]           = acc[nt][0];
            Cs[row0 * C_PITCH + col + 1]       = acc[nt][1];
            Cs[(row0 + 8) * C_PITCH + col]     = acc[nt][2];
            Cs[(row0 + 8) * C_PITCH + col + 1] = acc[nt][3];
        }
    }
    __syncthreads();

    // ---- logsumexp per row, scatter to original index ----
    if (tid < TILE_M) {
        const float* crow = &Cs[tid * C_PITCH];
        float mx = -3.4e38f;
#pragma unroll 8
        for (int j = 0; j < K_N; j++) mx = fmaxf(mx, crow[j] + ccombS[j]);
        float s = 0.f;
#pragma unroll 8
        for (int j = 0; j < K_N; j++) s += expf(crow[j] + ccombS[j] - mx);
        float ll = mx + logf(s);
        if (tid < nrows) out[rowIdxS[tid]] = ll;
    }
}

// ============================================================================
extern "C" void kernel_launch(void* const* d_in, const int* in_sizes, int n_in,
                              void* d_out, int out_size) {
    const float* x         = (const float*)d_in[0];
    const float* centroids = (const float*)d_in[1];
    const float* means     = (const float*)d_in[2];
    const float* log_stds  = (const float*)d_in[3];
    const float* logits    = (const float*)d_in[4];
    float* out = (float*)d_out;

    static bool attr_set = false;
    if (!attr_set) {
        cudaFuncSetAttribute(k4_gemm, cudaFuncAttributeMaxDynamicSharedMemorySize,
                             SM_TOTAL_K4);
        attr_set = true;
    }

    k0_prep   <<<E_N * K_N, 128>>>(centroids, means, log_stds, logits);
    k1_route  <<<B_N / 32,  256>>>(x, centroids);
    k3_scatter<<<B_N / 256, 256>>>();
    k4_gemm   <<<B_N / TILE_M + E_N, 512, SM_TOTAL_K4>>>(x, out);
}